// round 1
// baseline (speedup 1.0000x reference)
#include <cuda_runtime.h>
#include <cstdint>

// Problem constants
#define BB 32          // batch
#define II 2048        // in capsules
#define OO 32          // out capsules
#define CC 16          // in capsule dim
#define UU 32          // unit size
#define KTOT (II*CC)   // 32768 = GEMM K

#define IBLOCKS 32
#define ITILE (II/IBLOCKS)   // 64 i's per block
#define IW (ITILE/8)         // 8 i's per warp

// Scratch (no cudaMalloc allowed)
__device__ float g_xt[KTOT * BB];                    // x transposed: [k][b], 4MB
__device__ float g_spart[IBLOCKS * OO * UU * BB];    // partial s: [ib][o][u][b], 4MB

// ---------------------------------------------------------------------------
// Kernel A: transpose x [B, K] -> x_t [K, B]
// grid = KTOT/32 = 1024 blocks, 256 threads
// ---------------------------------------------------------------------------
__global__ void transpose_x(const float* __restrict__ x) {
    __shared__ float tile[32][33];
    const int k0  = blockIdx.x * 32;
    const int col = threadIdx.x & 31;
    const int row = threadIdx.x >> 5;   // 0..7
#pragma unroll
    for (int j = 0; j < 4; j++) {
        int b = row + j * 8;
        tile[b][col] = x[(size_t)b * KTOT + k0 + col];   // coalesced read
    }
    __syncthreads();
#pragma unroll
    for (int j = 0; j < 4; j++) {
        int kk = row + j * 8;
        g_xt[(size_t)(k0 + kk) * BB + col] = tile[col][kk];  // coalesced write
    }
}

// ---------------------------------------------------------------------------
// Kernel B: s_part[ib,o,u,b] = sum over i in tile, c of x[b,i,c]*w[i,o,c,u]
// grid = (IBLOCKS, OO), 256 threads (8 warps). lane = b.
// Each thread: fixed (b, o), accumulates all 32 u's as 16 packed f32x2 regs.
// ---------------------------------------------------------------------------
__global__ void __launch_bounds__(256, 2) gemm_k(const float* __restrict__ w) {
    const int ib   = blockIdx.x;
    const int o    = blockIdx.y;
    const int wid  = threadIdx.x >> 5;
    const int lane = threadIdx.x & 31;   // = b

    const int i0 = ib * ITILE + wid * IW;

    unsigned long long acc[16];
#pragma unroll
    for (int j = 0; j < 16; j++) acc[j] = 0ull;

    for (int ii = 0; ii < IW; ii++) {
        const int i = i0 + ii;
        // w row base: w[i][o][c][u], c stride = UU floats
        const ulonglong2* __restrict__ wrow =
            (const ulonglong2*)(w + ((size_t)(i * OO + o) * CC) * UU);
        const float* __restrict__ xp = g_xt + (size_t)(i * CC) * BB + lane;

#pragma unroll 4
        for (int c = 0; c < CC; c++) {
            float xv = xp[c * BB];                       // coalesced (lane = b)
            unsigned long long x2;
            asm("mov.b64 %0, {%1, %1};" : "=l"(x2) : "f"(xv));  // pack (xv, xv)

            const ulonglong2* wq = wrow + c * (UU / 4);  // 8 x 16B = 32 floats
#pragma unroll
            for (int j = 0; j < 8; j++) {
                ulonglong2 wv = wq[j];   // floats u = 4j .. 4j+3
                asm("fma.rn.f32x2 %0, %1, %2, %0;"
                    : "+l"(acc[2 * j])     : "l"(wv.x), "l"(x2));
                asm("fma.rn.f32x2 %0, %1, %2, %0;"
                    : "+l"(acc[2 * j + 1]) : "l"(wv.y), "l"(x2));
            }
        }
    }

    // Cross-warp reduction: acc[m] holds u = 2m (lo), 2m+1 (hi) for this b.
    __shared__ float red[8][32][32];   // [wid][u][b] = 32KB
#pragma unroll
    for (int m = 0; m < 16; m++) {
        unsigned lo = (unsigned)(acc[m] & 0xffffffffull);
        unsigned hi = (unsigned)(acc[m] >> 32);
        red[wid][2 * m][lane]     = __uint_as_float(lo);
        red[wid][2 * m + 1][lane] = __uint_as_float(hi);
    }
    __syncthreads();

#pragma unroll
    for (int r = 0; r < 4; r++) {
        int gid = threadIdx.x + 256 * r;       // gid = u*32 + b
        int u = gid >> 5, b = gid & 31;
        float s = 0.f;
#pragma unroll
        for (int ww = 0; ww < 8; ww++) s += red[ww][u][b];
        g_spart[((size_t)ib * OO + o) * (UU * BB) + gid] = s;   // coalesced
    }
}

// ---------------------------------------------------------------------------
// Kernel C: s[b,o,u] = sum_ib s_part; v = s * n / (1 + n^2), n = ||s||_u
// out[b][o][0][u] -> out[b*1024 + o*32 + u]
// grid = OO blocks, 256 threads
// ---------------------------------------------------------------------------
__global__ void reduce_squash(float* __restrict__ out) {
    const int o = blockIdx.x;
    const int t = threadIdx.x;
    __shared__ float sblk[UU * BB];    // [u*32 + b]
    __shared__ float scale_s[BB];

#pragma unroll
    for (int r = 0; r < 4; r++) {
        int gid = t + 256 * r;          // u*32 + b
        float s = 0.f;
#pragma unroll
        for (int ibk = 0; ibk < IBLOCKS; ibk++)
            s += g_spart[((size_t)ibk * OO + o) * (UU * BB) + gid];  // coalesced
        sblk[gid] = s;
    }
    __syncthreads();

    if (t < BB) {
        int b = t;
        float nsq = 0.f;
#pragma unroll
        for (int u = 0; u < UU; u++) {
            float sv = sblk[u * BB + b];
            nsq += sv * sv;
        }
        float n = sqrtf(nsq);
        scale_s[b] = n / (1.0f + nsq);
    }
    __syncthreads();

#pragma unroll
    for (int r = 0; r < 4; r++) {
        int gid = t + 256 * r;          // here: b*32 + u for coalesced output
        int b = gid >> 5, u = gid & 31;
        out[(size_t)b * (OO * UU) + o * UU + u] = sblk[u * BB + b] * scale_s[b];
    }
}

// ---------------------------------------------------------------------------
extern "C" void kernel_launch(void* const* d_in, const int* in_sizes, int n_in,
                              void* d_out, int out_size) {
    const float* x = (const float*)d_in[0];
    const float* w = (const float*)d_in[1];
    // x has B*I*C = 1,048,576 elems; w has I*O*C*U = 33,554,432. Guard ordering.
    if (n_in >= 2 && in_sizes[0] > in_sizes[1]) {
        x = (const float*)d_in[1];
        w = (const float*)d_in[0];
    }

    transpose_x<<<KTOT / 32, 256>>>(x);
    gemm_k<<<dim3(IBLOCKS, OO), 256>>>(w);
    reduce_squash<<<OO, 256>>>((float*)d_out);
}

// round 2
// speedup vs baseline: 2.6013x; 2.6013x over previous
#include <cuda_runtime.h>
#include <cstdint>

// Problem constants
#define BB 32          // batch
#define II 2048        // in capsules
#define OO 32          // out capsules
#define CC 16          // in capsule dim
#define UU 32          // unit size
#define KTOT (II*CC)   // 32768

// GEMM tiling
#define NIB    64              // i-blocks
#define ITILE  (II/NIB)        // 32 i's per block
#define OGRP   8               // o-groups (grid.y)
#define NOB    (OO/OGRP)       // 4 o's per block (one per warp)
#define CH     2               // i's per pipeline chunk
#define KCH    (CH*CC)         // 32 k-steps per chunk
#define NCHUNK (ITILE/CH)      // 16 chunks

// Scratch (no cudaMalloc allowed)
__device__ float g_xt[KTOT * BB];                 // x transposed [k][b], 4MB
__device__ float g_spart[NIB * OO * BB * UU];     // partials [ib][o][b][u], 8MB

// ---------------------------------------------------------------------------
// cp.async helpers
// ---------------------------------------------------------------------------
__device__ __forceinline__ void cp_async16(unsigned saddr, const void* gaddr) {
    asm volatile("cp.async.cg.shared.global [%0], [%1], 16;\n"
                 :: "r"(saddr), "l"(gaddr));
}
__device__ __forceinline__ void cp_commit() {
    asm volatile("cp.async.commit_group;\n");
}
template <int N>
__device__ __forceinline__ void cp_wait() {
    asm volatile("cp.async.wait_group %0;\n" :: "n"(N));
}

// ---------------------------------------------------------------------------
// Kernel A: transpose x [B, K] -> x_t [K, B]
// ---------------------------------------------------------------------------
__global__ void transpose_x(const float* __restrict__ x) {
    __shared__ float tile[32][33];
    const int k0  = blockIdx.x * 32;
    const int col = threadIdx.x & 31;
    const int row = threadIdx.x >> 5;
#pragma unroll
    for (int j = 0; j < 4; j++) {
        int b = row + j * 8;
        tile[b][col] = x[(size_t)b * KTOT + k0 + col];
    }
    __syncthreads();
#pragma unroll
    for (int j = 0; j < 4; j++) {
        int kk = row + j * 8;
        g_xt[(size_t)(k0 + kk) * BB + col] = tile[col][kk];
    }
}

// ---------------------------------------------------------------------------
// Kernel B: register-tiled GEMM with cp.async double-buffered smem staging.
// grid = (NIB, OGRP), 128 threads = 4 warps. Warp w handles o = o0 + w.
// Thread tile: 4 b x 8 u, acc as 16 packed f32x2 (pairs along u).
// ---------------------------------------------------------------------------
__global__ void __launch_bounds__(128, 4) gemm_k(const float* __restrict__ w) {
    // smem: double-buffered w chunk [CH][NOB][CC][UU] and x chunk [KCH][BB]
    __shared__ float ws[2][CH * NOB * CC * UU];   // 2 x 16KB
    __shared__ float xs[2][KCH * BB];             // 2 x 4KB

    const int ib  = blockIdx.x;
    const int o0  = blockIdx.y * NOB;
    const int tid = threadIdx.x;
    const int wid = tid >> 5;          // warp -> o index within block
    const int lane = tid & 31;
    const int bgrp = lane & 7;         // b0 = 4*bgrp
    const int ugrp = lane >> 3;        // u0 = 8*ugrp

    const int i_base = ib * ITILE;
    const size_t xk_base = (size_t)(i_base * CC) * BB;   // g_xt offset (floats)

    unsigned s_ws0 = (unsigned)__cvta_generic_to_shared(&ws[0][0]);
    unsigned s_ws1 = (unsigned)__cvta_generic_to_shared(&ws[1][0]);
    unsigned s_xs0 = (unsigned)__cvta_generic_to_shared(&xs[0][0]);
    unsigned s_xs1 = (unsigned)__cvta_generic_to_shared(&xs[1][0]);

    // ---- chunk load: w piece = per il, 4 o's contiguous = 2048 floats (8KB)
    //      x piece = 1024 floats (4KB) contiguous in g_xt
    auto issue_chunk = [&](int t, int p) {
        unsigned sw = p ? s_ws1 : s_ws0;
        unsigned sx = p ? s_xs1 : s_xs0;
#pragma unroll
        for (int il = 0; il < CH; il++) {
            const float* gsrc = w + ((size_t)((i_base + t * CH + il) * OO + o0) * CC) * UU;
#pragma unroll
            for (int r = 0; r < 4; r++) {
                int idx = r * 128 + tid;           // float4 index within 2048 floats
                cp_async16(sw + (il * 2048 + idx * 4) * 4, gsrc + idx * 4);
            }
        }
        const float* gx = g_xt + xk_base + (size_t)t * KCH * BB;
#pragma unroll
        for (int r = 0; r < 2; r++) {
            int idx = r * 128 + tid;               // float4 index within 1024 floats
            cp_async16(sx + idx * 16, gx + idx * 4);
        }
        cp_commit();
    };

    unsigned long long acc[16];
#pragma unroll
    for (int m = 0; m < 16; m++) acc[m] = 0ull;

    issue_chunk(0, 0);

    for (int t = 0; t < NCHUNK; t++) {
        const int p = t & 1;
        if (t + 1 < NCHUNK) {
            issue_chunk(t + 1, p ^ 1);
            cp_wait<1>();
        } else {
            cp_wait<0>();
        }
        __syncthreads();

        const float4* x4 = (const float4*)&xs[p][0];
        // w as 16B units: index ((il*NOB + o)*CC + c)*8 + ugrp*2
        const ulonglong2* w2 = (const ulonglong2*)&ws[p][0];
        const int wbase = wid * (CC * 8) + ugrp * 2;   // o term + u term

#pragma unroll
        for (int kk = 0; kk < KCH; kk++) {
            const int il = kk >> 4, c = kk & 15;
            float4 xv = x4[kk * 8 + bgrp];
            const int wi = il * (NOB * CC * 8) + c * 8 + wbase;
            ulonglong2 wq0 = w2[wi];        // u0..u0+3  (two f32x2)
            ulonglong2 wq1 = w2[wi + 1];    // u0+4..u0+7

            unsigned long long xb0, xb1, xb2, xb3;
            asm("mov.b64 %0, {%1, %1};" : "=l"(xb0) : "f"(xv.x));
            asm("mov.b64 %0, {%1, %1};" : "=l"(xb1) : "f"(xv.y));
            asm("mov.b64 %0, {%1, %1};" : "=l"(xb2) : "f"(xv.z));
            asm("mov.b64 %0, {%1, %1};" : "=l"(xb3) : "f"(xv.w));

#define FMA2(m, wv, xv2) asm("fma.rn.f32x2 %0, %1, %2, %0;" : "+l"(acc[m]) : "l"(wv), "l"(xv2))
            FMA2(0,  wq0.x, xb0); FMA2(1,  wq0.y, xb0); FMA2(2,  wq1.x, xb0); FMA2(3,  wq1.y, xb0);
            FMA2(4,  wq0.x, xb1); FMA2(5,  wq0.y, xb1); FMA2(6,  wq1.x, xb1); FMA2(7,  wq1.y, xb1);
            FMA2(8,  wq0.x, xb2); FMA2(9,  wq0.y, xb2); FMA2(10, wq1.x, xb2); FMA2(11, wq1.y, xb2);
            FMA2(12, wq0.x, xb3); FMA2(13, wq0.y, xb3); FMA2(14, wq1.x, xb3); FMA2(15, wq1.y, xb3);
#undef FMA2
        }
        __syncthreads();   // protect buffer p before it is refilled at t+2
    }

    // Epilogue: thread holds C[b0+b][u0+2up .. +1], b in 0..3, up in 0..3.
    // g_spart layout [ib][o][b][u]
    const int o = o0 + wid;
    float* outp = g_spart + ((size_t)(ib * OO + o) * BB) * UU;
#pragma unroll
    for (int b = 0; b < 4; b++) {
        int brow = (bgrp * 4 + b) * UU;
#pragma unroll
        for (int up = 0; up < 4; up++) {
            *(unsigned long long*)&outp[brow + ugrp * 8 + 2 * up] = acc[b * 4 + up];
        }
    }
}

// ---------------------------------------------------------------------------
// Kernel C: s[b,o,u] = sum_ib partial; v = s * n/(1+n^2), n = ||s||_u
// out[b][o][0][u]
// ---------------------------------------------------------------------------
__global__ void reduce_squash(float* __restrict__ out) {
    const int o = blockIdx.x;
    const int t = threadIdx.x;
    __shared__ float sblk[BB * UU];     // [b*32+u]
    __shared__ float scale_s[BB];

#pragma unroll
    for (int r = 0; r < 4; r++) {
        int gid = t + 256 * r;           // b*32+u
        float s = 0.f;
#pragma unroll
        for (int ibk = 0; ibk < NIB; ibk++)
            s += g_spart[((size_t)(ibk * OO + o)) * (BB * UU) + gid];
        sblk[gid] = s;
    }
    __syncthreads();

    if (t < BB) {
        float nsq = 0.f;
#pragma unroll
        for (int u = 0; u < UU; u++) {
            float sv = sblk[t * UU + u];
            nsq += sv * sv;
        }
        scale_s[t] = sqrtf(nsq) / (1.0f + nsq);
    }
    __syncthreads();

#pragma unroll
    for (int r = 0; r < 4; r++) {
        int gid = t + 256 * r;
        int b = gid >> 5, u = gid & 31;
        out[(size_t)b * (OO * UU) + o * UU + u] = sblk[gid] * scale_s[b];
    }
}

// ---------------------------------------------------------------------------
extern "C" void kernel_launch(void* const* d_in, const int* in_sizes, int n_in,
                              void* d_out, int out_size) {
    const float* x = (const float*)d_in[0];
    const float* w = (const float*)d_in[1];
    if (n_in >= 2 && in_sizes[0] > in_sizes[1]) {   // guard input ordering
        x = (const float*)d_in[1];
        w = (const float*)d_in[0];
    }

    transpose_x<<<KTOT / 32, 256>>>(x);
    gemm_k<<<dim3(NIB, OGRP), 128>>>(w);
    reduce_squash<<<OO, 256>>>((float*)d_out);
}

// round 4
// speedup vs baseline: 2.8002x; 1.0765x over previous
#include <cuda_runtime.h>
#include <cstdint>

// Problem constants
#define BB 32
#define II 2048
#define OO 32
#define CC 16
#define UU 32
#define KTOT (II*CC)        // 32768

// D[1024(m=o*32+u), 32(n=b)] = W^T * X^T
#define MT  8               // m-tiles of 128 rows (4 o x 32 u)
#define KS  64              // k-splits
#define KC  64              // k per chunk
#define NCH (KTOT/(KS*KC))  // 8 chunks per block

// Scratch partials [mt][ks][m_local(128)][b(32)] = 8MB
__device__ float g_spart[(size_t)MT * KS * 128 * BB];

// ---------------------------------------------------------------------------
__device__ __forceinline__ uint32_t smem_u32(const void* p) {
    uint32_t a;
    asm("{ .reg .u64 t; cvta.to.shared.u64 t, %1; cvt.u32.u64 %0, t; }"
        : "=r"(a) : "l"(p));
    return a;
}
// pack two f32 -> bf16x2, lo in bits[15:0] (first asm src goes to upper half)
__device__ __forceinline__ uint32_t pack_bf16(float lo, float hi) {
    uint32_t r;
    asm("cvt.rn.bf16x2.f32 %0, %1, %2;" : "=r"(r) : "f"(hi), "f"(lo));
    return r;
}
__device__ __forceinline__ void ldsm_x4(uint32_t* r, uint32_t addr) {
    asm volatile("ldmatrix.sync.aligned.m8n8.x4.shared.b16 {%0,%1,%2,%3}, [%4];"
                 : "=r"(r[0]), "=r"(r[1]), "=r"(r[2]), "=r"(r[3]) : "r"(addr));
}
__device__ __forceinline__ void mma_bf16(float* d, const uint32_t* a,
                                         uint32_t b0, uint32_t b1) {
    asm volatile(
        "mma.sync.aligned.m16n8k16.row.col.f32.bf16.bf16.f32 "
        "{%0,%1,%2,%3}, {%4,%5,%6,%7}, {%8,%9}, {%0,%1,%2,%3};"
        : "+f"(d[0]), "+f"(d[1]), "+f"(d[2]), "+f"(d[3])
        : "r"(a[0]), "r"(a[1]), "r"(a[2]), "r"(a[3]), "r"(b0), "r"(b1));
}

// ---------------------------------------------------------------------------
// GEMM: grid (MT, KS), 128 threads (4 warps; warp wid owns o = mt*4+wid,
// m rows wid*32..wid*32+31). Per chunk: fp32 -> bf16 hi/lo into swizzled smem,
// then 96 HMMA/warp (3 products: AhBh + AlBh + AhBl) into fp32 regs.
// ---------------------------------------------------------------------------
__global__ void __launch_bounds__(128) gemm_tc(const float* __restrict__ w,
                                               const float* __restrict__ x) {
    __shared__ __align__(128) uint8_t A_HI[128 * 128];   // [m(128)][k(64) bf16]
    __shared__ __align__(128) uint8_t A_LO[128 * 128];
    __shared__ __align__(128) uint8_t B_HI[32 * 128];    // [b(32)][k(64) bf16]
    __shared__ __align__(128) uint8_t B_LO[32 * 128];

    const int mt   = blockIdx.x;
    const int ks   = blockIdx.y;
    const int tid  = threadIdx.x;
    const int wid  = tid >> 5;
    const int lane = tid & 31;

    const int o = mt * 4 + wid;   // A-convert: row m = tid, (o, u=lane)
    const int u = lane;
    const int m = tid;

    const uint32_t aHi = smem_u32(A_HI), aLo = smem_u32(A_LO);
    const uint32_t bHi = smem_u32(B_HI), bLo = smem_u32(B_LO);

    const int xb = tid >> 2, xq = tid & 3;   // B-convert mapping

    float acc[2][4][4];
#pragma unroll
    for (int a = 0; a < 2; a++)
#pragma unroll
        for (int b = 0; b < 4; b++)
#pragma unroll
            for (int c = 0; c < 4; c++) acc[a][b][c] = 0.f;

    for (int t = 0; t < NCH; t++) {
        const int i0 = (ks * NCH + t) * 4;
        if (t) __syncthreads();   // chunk t-1's MMAs done before overwrite

        // ---- A tile: w rows for this m: k = i*16+c, i = i0..i0+3
        {
            const float* wp = w + (((size_t)i0 * OO + o) * CC) * UU + u;
#pragma unroll
            for (int j = 0; j < 8; j++) {          // 8 k's per group
                float v[8];
#pragma unroll
                for (int e = 0; e < 8; e++) {
                    const int kl = 8 * j + e;
                    v[e] = wp[(size_t)(kl >> 4) * (OO * CC * UU) + (kl & 15) * UU];
                }
                uint32_t h[4], l[4];
#pragma unroll
                for (int q = 0; q < 4; q++) {
                    h[q] = pack_bf16(v[2 * q], v[2 * q + 1]);
                    float r0 = v[2 * q]     - __uint_as_float(h[q] << 16);
                    float r1 = v[2 * q + 1] - __uint_as_float(h[q] & 0xffff0000u);
                    l[q] = pack_bf16(r0, r1);
                }
                const uint32_t off = (uint32_t)(m * 128 + ((j ^ (m & 7)) << 4));
                *(uint4*)(A_HI + off) = make_uint4(h[0], h[1], h[2], h[3]);
                *(uint4*)(A_LO + off) = make_uint4(l[0], l[1], l[2], l[3]);
            }
        }

        // ---- B tile: x[b][k] is k-contiguous (no transpose needed)
        {
            const float4* xp =
                (const float4*)(x + (size_t)xb * KTOT + ks * (NCH * KC) + t * KC)
                + xq * 4;
#pragma unroll
            for (int ff = 0; ff < 2; ff++) {
                float4 v0 = xp[2 * ff], v1 = xp[2 * ff + 1];
                float v[8] = {v0.x, v0.y, v0.z, v0.w, v1.x, v1.y, v1.z, v1.w};
                uint32_t h[4], l[4];
#pragma unroll
                for (int q = 0; q < 4; q++) {
                    h[q] = pack_bf16(v[2 * q], v[2 * q + 1]);
                    float r0 = v[2 * q]     - __uint_as_float(h[q] << 16);
                    float r1 = v[2 * q + 1] - __uint_as_float(h[q] & 0xffff0000u);
                    l[q] = pack_bf16(r0, r1);
                }
                const uint32_t g = (uint32_t)((2 * xq + ff) ^ (xb & 7));
                const uint32_t off = (uint32_t)(xb * 128 + g * 16);
                *(uint4*)(B_HI + off) = make_uint4(h[0], h[1], h[2], h[3]);
                *(uint4*)(B_LO + off) = make_uint4(l[0], l[1], l[2], l[3]);
            }
        }

        __syncthreads();

        // ---- MMA: 4 k-tiles of 16
#pragma unroll
        for (int kt = 0; kt < 4; kt++) {
            const int kg = 2 * kt;
            uint32_t ahi[2][4], alo[2][4], bhiR[2][4], bloR[2][4];

            // A fragments (x4 = [m0-7,k0-7],[m8-15,k0-7],[m0-7,k8-15],[m8-15,k8-15])
            const int ar  = (lane & 7) + ((lane >> 3) & 1) * 8;
            const int akg = kg + (lane >> 4);
#pragma unroll
            for (int m2 = 0; m2 < 2; m2++) {
                const int row = wid * 32 + m2 * 16 + ar;
                const uint32_t off = (uint32_t)(row * 128 + ((akg ^ (row & 7)) << 4));
                ldsm_x4(ahi[m2], aHi + off);
                ldsm_x4(alo[m2], aLo + off);
            }
            // B fragments (x4 = [n0-7,k0-7],[n0-7,k8-15],[n8-15,k0-7],[n8-15,k8-15])
            const int bn  = (lane & 7) + ((lane >> 4) & 1) * 8;
            const int bkg = kg + ((lane >> 3) & 1);
#pragma unroll
            for (int g2 = 0; g2 < 2; g2++) {
                const int n = g2 * 16 + bn;
                const uint32_t off = (uint32_t)(n * 128 + ((bkg ^ (n & 7)) << 4));
                ldsm_x4(bhiR[g2], bHi + off);
                ldsm_x4(bloR[g2], bLo + off);
            }
            // 2m x 4n x 3 products
#pragma unroll
            for (int m2 = 0; m2 < 2; m2++)
#pragma unroll
                for (int nt = 0; nt < 4; nt++) {
                    const uint32_t bh0 = bhiR[nt >> 1][(nt & 1) * 2];
                    const uint32_t bh1 = bhiR[nt >> 1][(nt & 1) * 2 + 1];
                    const uint32_t bl0 = bloR[nt >> 1][(nt & 1) * 2];
                    const uint32_t bl1 = bloR[nt >> 1][(nt & 1) * 2 + 1];
                    mma_bf16(acc[m2][nt], ahi[m2], bh0, bh1);
                    mma_bf16(acc[m2][nt], alo[m2], bh0, bh1);
                    mma_bf16(acc[m2][nt], ahi[m2], bl0, bl1);
                }
        }
    }

    // ---- epilogue: D fragment -> g_spart[(mt*KS+ks)][m_local][b]
    float* outp = g_spart + ((size_t)(mt * KS + ks)) * (128 * BB);
#pragma unroll
    for (int m2 = 0; m2 < 2; m2++)
#pragma unroll
        for (int nt = 0; nt < 4; nt++) {
            const int r0 = wid * 32 + m2 * 16 + (lane >> 2);
            const int c  = nt * 8 + 2 * (lane & 3);
            *(float2*)(outp + (size_t)r0 * BB + c) =
                make_float2(acc[m2][nt][0], acc[m2][nt][1]);
            *(float2*)(outp + (size_t)(r0 + 8) * BB + c) =
                make_float2(acc[m2][nt][2], acc[m2][nt][3]);
        }
}

// ---------------------------------------------------------------------------
// Reduce over KS partials + squash. grid = 32 (o), 256 threads.
// m_local = (o%4)*32 + u, mt = o/4.  out[b][o][0][u]
// ---------------------------------------------------------------------------
__global__ void reduce_squash(float* __restrict__ out) {
    const int o = blockIdx.x;
    const int t = threadIdx.x;
    const int mt = o >> 2;
    const int mbase = (o & 3) * 32;

    __shared__ float sblk[UU * BB];    // [u*32 + b]
    __shared__ float scale_s[BB];

#pragma unroll
    for (int r = 0; r < 4; r++) {
        const int gid = t + 256 * r;
        const int u = gid >> 5, b = gid & 31;
        float s = 0.f;
#pragma unroll 8
        for (int ksv = 0; ksv < KS; ksv++)
            s += g_spart[(((size_t)mt * KS + ksv) * 128 + mbase + u) * BB + b];
        sblk[gid] = s;
    }
    __syncthreads();

    if (t < BB) {
        float nsq = 0.f;
#pragma unroll
        for (int u = 0; u < UU; u++) {
            float sv = sblk[u * BB + t];
            nsq += sv * sv;
        }
        scale_s[t] = sqrtf(nsq) / (1.0f + nsq);
    }
    __syncthreads();

#pragma unroll
    for (int r = 0; r < 4; r++) {
        const int gid = t + 256 * r;
        const int b = gid >> 5, u = gid & 31;
        out[(size_t)b * (OO * UU) + o * UU + u] = sblk[u * BB + b] * scale_s[b];
    }
}

// ---------------------------------------------------------------------------
extern "C" void kernel_launch(void* const* d_in, const int* in_sizes, int n_in,
                              void* d_out, int out_size) {
    const float* x = (const float*)d_in[0];
    const float* w = (const float*)d_in[1];
    if (n_in >= 2 && in_sizes[0] > in_sizes[1]) {   // guard input ordering
        x = (const float*)d_in[1];
        w = (const float*)d_in[0];
    }

    gemm_tc<<<dim3(MT, KS), 128>>>(w, x);
    reduce_squash<<<OO, 256>>>((float*)d_out);
}

// round 5
// speedup vs baseline: 3.3505x; 1.1965x over previous
#include <cuda_runtime.h>
#include <cstdint>

// Problem constants
#define BB 32
#define II 2048
#define OO 32
#define CC 16
#define UU 32
#define KTOT (II*CC)        // 32768

// D[1024(m=o*32+u), 32(n=b)] = W^T * X^T
#define MT  8               // m-tiles of 128 rows (4 o x 32 u)
#define KS  64              // k-splits
#define KC  64              // k per chunk
#define NCH (KTOT/(KS*KC))  // 8 chunks per block

// Scratch partials [mt][ks][m_local(128)][b(32)] = 8MB
__device__ float g_spart[(size_t)MT * KS * 128 * BB];

// ---------------------------------------------------------------------------
__device__ __forceinline__ uint32_t smem_u32(const void* p) {
    uint32_t a;
    asm("{ .reg .u64 t; cvta.to.shared.u64 t, %1; cvt.u32.u64 %0, t; }"
        : "=r"(a) : "l"(p));
    return a;
}
// pack two f32 -> bf16x2, lo in bits[15:0] (first asm src goes to upper half)
__device__ __forceinline__ uint32_t pack_bf16(float lo, float hi) {
    uint32_t r;
    asm("cvt.rn.bf16x2.f32 %0, %1, %2;" : "=r"(r) : "f"(hi), "f"(lo));
    return r;
}
__device__ __forceinline__ void ldsm_x4(uint32_t* r, uint32_t addr) {
    asm volatile("ldmatrix.sync.aligned.m8n8.x4.shared.b16 {%0,%1,%2,%3}, [%4];"
                 : "=r"(r[0]), "=r"(r[1]), "=r"(r[2]), "=r"(r[3]) : "r"(addr));
}
__device__ __forceinline__ void mma_bf16(float* d, const uint32_t* a,
                                         uint32_t b0, uint32_t b1) {
    asm volatile(
        "mma.sync.aligned.m16n8k16.row.col.f32.bf16.bf16.f32 "
        "{%0,%1,%2,%3}, {%4,%5,%6,%7}, {%8,%9}, {%0,%1,%2,%3};"
        : "+f"(d[0]), "+f"(d[1]), "+f"(d[2]), "+f"(d[3])
        : "r"(a[0]), "r"(a[1]), "r"(a[2]), "r"(a[3]), "r"(b0), "r"(b1));
}

// ---------------------------------------------------------------------------
// GEMM: grid (MT, KS), 128 threads (4 warps; warp wid owns o = mt*4+wid,
// m rows wid*32..wid*32+31). Per chunk: fp32 -> bf16 hi/lo into swizzled smem,
// then 96 HMMA/warp (3 products: AhBh + AlBh + AhBl) into fp32 regs.
// ---------------------------------------------------------------------------
__global__ void __launch_bounds__(128) gemm_tc(const float* __restrict__ w,
                                               const float* __restrict__ x) {
    __shared__ __align__(128) uint8_t A_HI[128 * 128];   // [m(128)][k(64) bf16]
    __shared__ __align__(128) uint8_t A_LO[128 * 128];
    __shared__ __align__(128) uint8_t B_HI[32 * 128];    // [b(32)][k(64) bf16]
    __shared__ __align__(128) uint8_t B_LO[32 * 128];

    const int mt   = blockIdx.x;
    const int ks   = blockIdx.y;
    const int tid  = threadIdx.x;
    const int wid  = tid >> 5;
    const int lane = tid & 31;

    const int o = mt * 4 + wid;   // A-convert: row m = tid, (o, u=lane)
    const int u = lane;
    const int m = tid;

    const uint32_t aHi = smem_u32(A_HI), aLo = smem_u32(A_LO);
    const uint32_t bHi = smem_u32(B_HI), bLo = smem_u32(B_LO);

    const int xb = tid >> 2, xq = tid & 3;   // B-convert mapping

    float acc[2][4][4];
#pragma unroll
    for (int a = 0; a < 2; a++)
#pragma unroll
        for (int b = 0; b < 4; b++)
#pragma unroll
            for (int c = 0; c < 4; c++) acc[a][b][c] = 0.f;

    for (int t = 0; t < NCH; t++) {
        const int i0 = (ks * NCH + t) * 4;
        if (t) __syncthreads();   // chunk t-1's MMAs done before overwrite

        // ---- A tile: w rows for this m: k = i*16+c, i = i0..i0+3
        {
            const float* wp = w + (((size_t)i0 * OO + o) * CC) * UU + u;
#pragma unroll
            for (int j = 0; j < 8; j++) {          // 8 k's per group
                float v[8];
#pragma unroll
                for (int e = 0; e < 8; e++) {
                    const int kl = 8 * j + e;
                    v[e] = wp[(size_t)(kl >> 4) * (OO * CC * UU) + (kl & 15) * UU];
                }
                uint32_t h[4], l[4];
#pragma unroll
                for (int q = 0; q < 4; q++) {
                    h[q] = pack_bf16(v[2 * q], v[2 * q + 1]);
                    float r0 = v[2 * q]     - __uint_as_float(h[q] << 16);
                    float r1 = v[2 * q + 1] - __uint_as_float(h[q] & 0xffff0000u);
                    l[q] = pack_bf16(r0, r1);
                }
                const uint32_t off = (uint32_t)(m * 128 + ((j ^ (m & 7)) << 4));
                *(uint4*)(A_HI + off) = make_uint4(h[0], h[1], h[2], h[3]);
                *(uint4*)(A_LO + off) = make_uint4(l[0], l[1], l[2], l[3]);
            }
        }

        // ---- B tile: x[b][k] is k-contiguous (no transpose needed)
        {
            const float4* xp =
                (const float4*)(x + (size_t)xb * KTOT + ks * (NCH * KC) + t * KC)
                + xq * 4;
#pragma unroll
            for (int ff = 0; ff < 2; ff++) {
                float4 v0 = xp[2 * ff], v1 = xp[2 * ff + 1];
                float v[8] = {v0.x, v0.y, v0.z, v0.w, v1.x, v1.y, v1.z, v1.w};
                uint32_t h[4], l[4];
#pragma unroll
                for (int q = 0; q < 4; q++) {
                    h[q] = pack_bf16(v[2 * q], v[2 * q + 1]);
                    float r0 = v[2 * q]     - __uint_as_float(h[q] << 16);
                    float r1 = v[2 * q + 1] - __uint_as_float(h[q] & 0xffff0000u);
                    l[q] = pack_bf16(r0, r1);
                }
                const uint32_t g = (uint32_t)((2 * xq + ff) ^ (xb & 7));
                const uint32_t off = (uint32_t)(xb * 128 + g * 16);
                *(uint4*)(B_HI + off) = make_uint4(h[0], h[1], h[2], h[3]);
                *(uint4*)(B_LO + off) = make_uint4(l[0], l[1], l[2], l[3]);
            }
        }

        __syncthreads();

        // ---- MMA: 4 k-tiles of 16
#pragma unroll
        for (int kt = 0; kt < 4; kt++) {
            const int kg = 2 * kt;
            uint32_t ahi[2][4], alo[2][4], bhiR[2][4], bloR[2][4];

            const int ar  = (lane & 7) + ((lane >> 3) & 1) * 8;
            const int akg = kg + (lane >> 4);
#pragma unroll
            for (int m2 = 0; m2 < 2; m2++) {
                const int row = wid * 32 + m2 * 16 + ar;
                const uint32_t off = (uint32_t)(row * 128 + ((akg ^ (row & 7)) << 4));
                ldsm_x4(ahi[m2], aHi + off);
                ldsm_x4(alo[m2], aLo + off);
            }
            const int bn  = (lane & 7) + ((lane >> 4) & 1) * 8;
            const int bkg = kg + ((lane >> 3) & 1);
#pragma unroll
            for (int g2 = 0; g2 < 2; g2++) {
                const int n = g2 * 16 + bn;
                const uint32_t off = (uint32_t)(n * 128 + ((bkg ^ (n & 7)) << 4));
                ldsm_x4(bhiR[g2], bHi + off);
                ldsm_x4(bloR[g2], bLo + off);
            }
#pragma unroll
            for (int m2 = 0; m2 < 2; m2++)
#pragma unroll
                for (int nt = 0; nt < 4; nt++) {
                    const uint32_t bh0 = bhiR[nt >> 1][(nt & 1) * 2];
                    const uint32_t bh1 = bhiR[nt >> 1][(nt & 1) * 2 + 1];
                    const uint32_t bl0 = bloR[nt >> 1][(nt & 1) * 2];
                    const uint32_t bl1 = bloR[nt >> 1][(nt & 1) * 2 + 1];
                    mma_bf16(acc[m2][nt], ahi[m2], bh0, bh1);
                    mma_bf16(acc[m2][nt], alo[m2], bh0, bh1);
                    mma_bf16(acc[m2][nt], ahi[m2], bl0, bl1);
                }
        }
    }

    // ---- epilogue: D fragment -> g_spart[(mt*KS+ks)][m_local][b]
    float* outp = g_spart + ((size_t)(mt * KS + ks)) * (128 * BB);
#pragma unroll
    for (int m2 = 0; m2 < 2; m2++)
#pragma unroll
        for (int nt = 0; nt < 4; nt++) {
            const int r0 = wid * 32 + m2 * 16 + (lane >> 2);
            const int c  = nt * 8 + 2 * (lane & 3);
            *(float2*)(outp + (size_t)r0 * BB + c) =
                make_float2(acc[m2][nt][0], acc[m2][nt][1]);
            *(float2*)(outp + (size_t)(r0 + 8) * BB + c) =
                make_float2(acc[m2][nt][2], acc[m2][nt][3]);
        }
}

// ---------------------------------------------------------------------------
// Fused reduce + squash. grid = 32 (o), 1024 threads.
// Thread (u = tid>>5, b = tid&31) sums its 64 k-split partials (coalesced:
// warp spans 32 consecutive b), then per-b norm over u via padded smem.
// out[b][o][0][u], warp-coalesced writes.
// ---------------------------------------------------------------------------
__global__ void __launch_bounds__(1024) reduce_squash(float* __restrict__ out) {
    const int o = blockIdx.x;
    const int t = threadIdx.x;
    const int mt = o >> 2;
    const int mrow = (o & 3) * 32 + (t >> 5);   // m_local for this thread's u
    const int b = t & 31;

    __shared__ float sblk[UU * 33];     // [u][b] padded stride 33
    __shared__ float scale_s[BB];

    const float* p = g_spart + (((size_t)mt * KS) * 128 + mrow) * BB + b;
    float s = 0.f;
#pragma unroll 8
    for (int ksv = 0; ksv < KS; ksv++)
        s += p[(size_t)ksv * (128 * BB)];
    sblk[(t >> 5) * 33 + b] = s;
    __syncthreads();

    if (t < BB) {
        float nsq = 0.f;
#pragma unroll
        for (int u = 0; u < UU; u++) {
            float sv = sblk[u * 33 + t];
            nsq += sv * sv;
        }
        scale_s[t] = sqrtf(nsq) / (1.0f + nsq);
    }
    __syncthreads();

    {   // remap: b2 = t>>5, u2 = t&31 -> coalesced 128B writes per warp
        const int b2 = t >> 5, u2 = t & 31;
        out[(size_t)b2 * (OO * UU) + o * UU + u2] =
            sblk[u2 * 33 + b2] * scale_s[b2];
    }
}

// ---------------------------------------------------------------------------
extern "C" void kernel_launch(void* const* d_in, const int* in_sizes, int n_in,
                              void* d_out, int out_size) {
    const float* x = (const float*)d_in[0];
    const float* w = (const float*)d_in[1];
    if (n_in >= 2 && in_sizes[0] > in_sizes[1]) {   // guard input ordering
        x = (const float*)d_in[1];
        w = (const float*)d_in[0];
    }

    gemm_tc<<<dim3(MT, KS), 128>>>(w, x);
    reduce_squash<<<OO, 1024>>>((float*)d_out);
}

// round 6
// speedup vs baseline: 3.6543x; 1.0907x over previous
#include <cuda_runtime.h>
#include <cstdint>

// Problem constants
#define BB 32
#define II 2048
#define OO 32
#define CC 16
#define UU 32
#define KTOT (II*CC)        // 32768

// D[1024(m=o*32+u), 32(n=b)] = W^T * X^T
#define MT  8               // m-tiles of 128 rows (4 o x 32 u)
#define KS  64              // k-splits
#define KC  64              // k per chunk
#define NCH (KTOT/(KS*KC))  // 8 chunks per block
#define NSEG 8              // reduce stage-1 segments (KS/NSEG k-splits each)

// Scratch: partials [mt][ks][m_local(128)][b(32)] = 8MB, stage1 = 1MB
__device__ float g_spart[(size_t)MT * KS * 128 * BB];
__device__ float g_s1[(size_t)OO * NSEG * UU * BB];

// ---------------------------------------------------------------------------
__device__ __forceinline__ uint32_t smem_u32(const void* p) {
    uint32_t a;
    asm("{ .reg .u64 t; cvta.to.shared.u64 t, %1; cvt.u32.u64 %0, t; }"
        : "=r"(a) : "l"(p));
    return a;
}
// pack two f32 -> bf16x2, lo in bits[15:0]
__device__ __forceinline__ uint32_t pack_bf16(float lo, float hi) {
    uint32_t r;
    asm("cvt.rn.bf16x2.f32 %0, %1, %2;" : "=r"(r) : "f"(hi), "f"(lo));
    return r;
}
__device__ __forceinline__ void ldsm_x4(uint32_t* r, uint32_t addr) {
    asm volatile("ldmatrix.sync.aligned.m8n8.x4.shared.b16 {%0,%1,%2,%3}, [%4];"
                 : "=r"(r[0]), "=r"(r[1]), "=r"(r[2]), "=r"(r[3]) : "r"(addr));
}
__device__ __forceinline__ void mma_bf16(float* d, const uint32_t* a,
                                         uint32_t b0, uint32_t b1) {
    asm volatile(
        "mma.sync.aligned.m16n8k16.row.col.f32.bf16.bf16.f32 "
        "{%0,%1,%2,%3}, {%4,%5,%6,%7}, {%8,%9}, {%0,%1,%2,%3};"
        : "+f"(d[0]), "+f"(d[1]), "+f"(d[2]), "+f"(d[3])
        : "r"(a[0]), "r"(a[1]), "r"(a[2]), "r"(a[3]), "r"(b0), "r"(b1));
}

// ---------------------------------------------------------------------------
// GEMM: grid (MT, KS), 128 threads. Software-pipelined: registers prefetch
// chunk t+1's global data while chunk t's MMAs run.
// ---------------------------------------------------------------------------
__global__ void __launch_bounds__(128) gemm_tc(const float* __restrict__ w,
                                               const float* __restrict__ x) {
    __shared__ __align__(128) uint8_t A_HI[128 * 128];   // [m][k(64) bf16]
    __shared__ __align__(128) uint8_t A_LO[128 * 128];
    __shared__ __align__(128) uint8_t B_HI[32 * 128];    // [b][k(64) bf16]
    __shared__ __align__(128) uint8_t B_LO[32 * 128];

    const int mt   = blockIdx.x;
    const int ks   = blockIdx.y;
    const int tid  = threadIdx.x;
    const int wid  = tid >> 5;
    const int lane = tid & 31;

    const int o = mt * 4 + wid;
    const int u = lane;
    const int m = tid;

    const uint32_t aHi = smem_u32(A_HI), aLo = smem_u32(A_LO);
    const uint32_t bHi = smem_u32(B_HI), bLo = smem_u32(B_LO);

    const int xb = tid >> 2, xq = tid & 3;

    const float* const wbase = w + (((size_t)(ks * NCH * 4) * OO + o) * CC) * UU + u;
    const float4* const xbase =
        (const float4*)(x + (size_t)xb * KTOT + ks * (NCH * KC)) + xq * 4;

    float va[64];
    float4 vb[4];

    // prefetch chunk 0
#pragma unroll
    for (int e = 0; e < 64; e++)
        va[e] = wbase[(size_t)(e >> 4) * (OO * CC * UU) + (e & 15) * UU];
#pragma unroll
    for (int f = 0; f < 4; f++) vb[f] = xbase[f];

    float acc[2][4][4];
#pragma unroll
    for (int a = 0; a < 2; a++)
#pragma unroll
        for (int b = 0; b < 4; b++)
#pragma unroll
            for (int c = 0; c < 4; c++) acc[a][b][c] = 0.f;

    for (int t = 0; t < NCH; t++) {
        // ---- convert & store chunk t (consumes va/vb)
#pragma unroll
        for (int j = 0; j < 8; j++) {
            uint32_t h[4], l[4];
#pragma unroll
            for (int q = 0; q < 4; q++) {
                float v0 = va[8 * j + 2 * q], v1 = va[8 * j + 2 * q + 1];
                h[q] = pack_bf16(v0, v1);
                float r0 = v0 - __uint_as_float(h[q] << 16);
                float r1 = v1 - __uint_as_float(h[q] & 0xffff0000u);
                l[q] = pack_bf16(r0, r1);
            }
            const uint32_t off = (uint32_t)(m * 128 + ((j ^ (m & 7)) << 4));
            *(uint4*)(A_HI + off) = make_uint4(h[0], h[1], h[2], h[3]);
            *(uint4*)(A_LO + off) = make_uint4(l[0], l[1], l[2], l[3]);
        }
#pragma unroll
        for (int ff = 0; ff < 2; ff++) {
            float4 v0 = vb[2 * ff], v1 = vb[2 * ff + 1];
            float v[8] = {v0.x, v0.y, v0.z, v0.w, v1.x, v1.y, v1.z, v1.w};
            uint32_t h[4], l[4];
#pragma unroll
            for (int q = 0; q < 4; q++) {
                h[q] = pack_bf16(v[2 * q], v[2 * q + 1]);
                float r0 = v[2 * q]     - __uint_as_float(h[q] << 16);
                float r1 = v[2 * q + 1] - __uint_as_float(h[q] & 0xffff0000u);
                l[q] = pack_bf16(r0, r1);
            }
            const uint32_t g = (uint32_t)((2 * xq + ff) ^ (xb & 7));
            const uint32_t off = (uint32_t)(xb * 128 + g * 16);
            *(uint4*)(B_HI + off) = make_uint4(h[0], h[1], h[2], h[3]);
            *(uint4*)(B_LO + off) = make_uint4(l[0], l[1], l[2], l[3]);
        }

        __syncthreads();

        // ---- prefetch chunk t+1 (LDG latency hides under the MMA loop)
        if (t + 1 < NCH) {
            const float* wp = wbase + (size_t)((t + 1) * 4) * (OO * CC * UU);
#pragma unroll
            for (int e = 0; e < 64; e++)
                va[e] = wp[(size_t)(e >> 4) * (OO * CC * UU) + (e & 15) * UU];
            const float4* xp = xbase + (t + 1) * (KC / 4);
#pragma unroll
            for (int f = 0; f < 4; f++) vb[f] = xp[f];
        }

        // ---- MMA: 4 k-tiles of 16
#pragma unroll
        for (int kt = 0; kt < 4; kt++) {
            const int kg = 2 * kt;
            uint32_t ahi[2][4], alo[2][4], bhiR[2][4], bloR[2][4];

            const int ar  = (lane & 7) + ((lane >> 3) & 1) * 8;
            const int akg = kg + (lane >> 4);
#pragma unroll
            for (int m2 = 0; m2 < 2; m2++) {
                const int row = wid * 32 + m2 * 16 + ar;
                const uint32_t off = (uint32_t)(row * 128 + ((akg ^ (row & 7)) << 4));
                ldsm_x4(ahi[m2], aHi + off);
                ldsm_x4(alo[m2], aLo + off);
            }
            const int bn  = (lane & 7) + ((lane >> 4) & 1) * 8;
            const int bkg = kg + ((lane >> 3) & 1);
#pragma unroll
            for (int g2 = 0; g2 < 2; g2++) {
                const int n = g2 * 16 + bn;
                const uint32_t off = (uint32_t)(n * 128 + ((bkg ^ (n & 7)) << 4));
                ldsm_x4(bhiR[g2], bHi + off);
                ldsm_x4(bloR[g2], bLo + off);
            }
#pragma unroll
            for (int m2 = 0; m2 < 2; m2++)
#pragma unroll
                for (int nt = 0; nt < 4; nt++) {
                    const uint32_t bh0 = bhiR[nt >> 1][(nt & 1) * 2];
                    const uint32_t bh1 = bhiR[nt >> 1][(nt & 1) * 2 + 1];
                    const uint32_t bl0 = bloR[nt >> 1][(nt & 1) * 2];
                    const uint32_t bl1 = bloR[nt >> 1][(nt & 1) * 2 + 1];
                    mma_bf16(acc[m2][nt], ahi[m2], bh0, bh1);
                    mma_bf16(acc[m2][nt], alo[m2], bh0, bh1);
                    mma_bf16(acc[m2][nt], ahi[m2], bl0, bl1);
                }
        }
        __syncthreads();
    }

    // ---- epilogue
    float* outp = g_spart + ((size_t)(mt * KS + ks)) * (128 * BB);
#pragma unroll
    for (int m2 = 0; m2 < 2; m2++)
#pragma unroll
        for (int nt = 0; nt < 4; nt++) {
            const int r0 = wid * 32 + m2 * 16 + (lane >> 2);
            const int c  = nt * 8 + 2 * (lane & 3);
            *(float2*)(outp + (size_t)r0 * BB + c) =
                make_float2(acc[m2][nt][0], acc[m2][nt][1]);
            *(float2*)(outp + (size_t)(r0 + 8) * BB + c) =
                make_float2(acc[m2][nt][2], acc[m2][nt][3]);
        }
}

// ---------------------------------------------------------------------------
// Reduce stage 1: grid (OO, NSEG), 1024 threads. Sums KS/NSEG=8 k-splits.
// ---------------------------------------------------------------------------
__global__ void __launch_bounds__(1024) reduce1() {
    const int o = blockIdx.x, seg = blockIdx.y;
    const int t = threadIdx.x;
    const int uu2 = t >> 5, b = t & 31;
    const int mt = o >> 2;
    const int mrow = (o & 3) * 32 + uu2;

    const float* p = g_spart +
        (((size_t)mt * KS + seg * (KS / NSEG)) * 128 + mrow) * BB + b;
    float s = 0.f;
#pragma unroll
    for (int k = 0; k < KS / NSEG; k++)
        s += p[(size_t)k * (128 * BB)];
    g_s1[(((size_t)o * NSEG + seg) * UU + uu2) * BB + b] = s;
}

// ---------------------------------------------------------------------------
// Reduce stage 2 + squash: grid = OO, 1024 threads.
// ---------------------------------------------------------------------------
__global__ void __launch_bounds__(1024) reduce2(float* __restrict__ out) {
    const int o = blockIdx.x;
    const int t = threadIdx.x;
    const int uu2 = t >> 5, b = t & 31;

    __shared__ float sblk[UU * 33];
    __shared__ float scale_s[BB];

    float s = 0.f;
#pragma unroll
    for (int seg = 0; seg < NSEG; seg++)
        s += g_s1[(((size_t)o * NSEG + seg) * UU + uu2) * BB + b];
    sblk[uu2 * 33 + b] = s;
    __syncthreads();

    if (t < BB) {
        float nsq = 0.f;
#pragma unroll
        for (int uv = 0; uv < UU; uv++) {
            float sv = sblk[uv * 33 + t];
            nsq += sv * sv;
        }
        scale_s[t] = sqrtf(nsq) / (1.0f + nsq);
    }
    __syncthreads();

    {   // coalesced output: b2 = t>>5, u2 = t&31
        const int b2 = t >> 5, u2 = t & 31;
        out[(size_t)b2 * (OO * UU) + o * UU + u2] =
            sblk[u2 * 33 + b2] * scale_s[b2];
    }
}

// ---------------------------------------------------------------------------
extern "C" void kernel_launch(void* const* d_in, const int* in_sizes, int n_in,
                              void* d_out, int out_size) {
    const float* x = (const float*)d_in[0];
    const float* w = (const float*)d_in[1];
    if (n_in >= 2 && in_sizes[0] > in_sizes[1]) {   // guard input ordering
        x = (const float*)d_in[1];
        w = (const float*)d_in[0];
    }

    gemm_tc<<<dim3(MT, KS), 128>>>(w, x);
    reduce1<<<dim3(OO, NSEG), 1024>>>();
    reduce2<<<OO, 1024>>>((float*)d_out);
}

// round 7
// speedup vs baseline: 4.3154x; 1.1809x over previous
#include <cuda_runtime.h>
#include <cstdint>

// Problem constants
#define BB 32
#define II 2048
#define OO 32
#define CC 16
#define UU 32
#define KTOT (II*CC)        // 32768

// D[1024(m=o*32+u), 32(n=b)] = W^T * X^T
#define MT  8               // m-tiles of 128 rows (4 o x 32 u)
#define KS  64              // k-splits
#define KC  32              // k per chunk (2 i's)
#define NCH (KTOT/(KS*KC))  // 16 chunks per block
#define NSEG 8              // reduce stage-1 segments

#define ISTRIDE (OO*CC*UU)  // floats between consecutive i in w

// Scratch: partials [mt][ks][m_local(128)][b(32)] = 8MB, stage1 = 1MB
__device__ float g_spart[(size_t)MT * KS * 128 * BB];
__device__ float g_s1[(size_t)OO * NSEG * UU * BB];

// ---------------------------------------------------------------------------
__device__ __forceinline__ uint32_t smem_u32(const void* p) {
    uint32_t a;
    asm("{ .reg .u64 t; cvta.to.shared.u64 t, %1; cvt.u32.u64 %0, t; }"
        : "=r"(a) : "l"(p));
    return a;
}
// pack two f32 -> bf16x2, lo in bits[15:0]
__device__ __forceinline__ uint32_t pack_bf16(float lo, float hi) {
    uint32_t r;
    asm("cvt.rn.bf16x2.f32 %0, %1, %2;" : "=r"(r) : "f"(hi), "f"(lo));
    return r;
}
__device__ __forceinline__ void ldsm_x4(uint32_t* r, uint32_t addr) {
    asm volatile("ldmatrix.sync.aligned.m8n8.x4.shared.b16 {%0,%1,%2,%3}, [%4];"
                 : "=r"(r[0]), "=r"(r[1]), "=r"(r[2]), "=r"(r[3]) : "r"(addr));
}
__device__ __forceinline__ void mma_bf16(float* d, const uint32_t* a,
                                         uint32_t b0, uint32_t b1) {
    asm volatile(
        "mma.sync.aligned.m16n8k16.row.col.f32.bf16.bf16.f32 "
        "{%0,%1,%2,%3}, {%4,%5,%6,%7}, {%8,%9}, {%0,%1,%2,%3};"
        : "+f"(d[0]), "+f"(d[1]), "+f"(d[2]), "+f"(d[3])
        : "r"(a[0]), "r"(a[1]), "r"(a[2]), "r"(a[3]), "r"(b0), "r"(b1));
}

// 64B-row swizzle: 16B group j of row r lives at r*64 + (j ^ ((r>>1)&3))*16
__device__ __forceinline__ uint32_t sw64(int row, int grp) {
    return (uint32_t)(row * 64 + ((grp ^ ((row >> 1) & 3)) << 4));
}

// ---------------------------------------------------------------------------
// GEMM: grid (MT, KS), 128 threads, 4 CTAs/SM.
// Per chunk (k=32): convert prefetched fp32 -> bf16 hi/lo into double-buffered
// swizzled smem; one sync; prefetch next chunk; 48 HMMA/warp (3 products).
// ---------------------------------------------------------------------------
__global__ void __launch_bounds__(128, 4) gemm_tc(const float* __restrict__ w,
                                                  const float* __restrict__ x) {
    // double-buffered: A 128x32 bf16 = 8KB, B 32x32 bf16 = 2KB (hi & lo each)
    __shared__ __align__(128) uint8_t A_HI[2][128 * 64];
    __shared__ __align__(128) uint8_t A_LO[2][128 * 64];
    __shared__ __align__(128) uint8_t B_HI[2][32 * 64];
    __shared__ __align__(128) uint8_t B_LO[2][32 * 64];

    const int mt   = blockIdx.x;
    const int ks   = blockIdx.y;
    const int tid  = threadIdx.x;
    const int wid  = tid >> 5;
    const int lane = tid & 31;

    const int o = mt * 4 + wid;      // A-convert: row m = tid = (o_local, u)
    const int u = lane;
    const int m = tid;

    const int xb = tid >> 2, xq = tid & 3;   // B-convert mapping

    // w base for this thread's (o, u); chunk t adds t*2*ISTRIDE
    const float* const wbase =
        w + (((size_t)(ks * NCH * 2) * OO + o) * CC) * UU + u;
    // x base: thread's b row, block's k segment; chunk t adds t*KC floats
    const float4* const xbase =
        (const float4*)(x + (size_t)xb * KTOT + ks * (NCH * KC)) + xq * 2;

    float  va[32];
    float4 vb[2];

    // prefetch chunk 0
#pragma unroll
    for (int e = 0; e < 32; e++)
        va[e] = wbase[(size_t)(e >> 4) * ISTRIDE + (e & 15) * UU];
    vb[0] = xbase[0];
    vb[1] = xbase[1];

    float acc[2][4][4];
#pragma unroll
    for (int a = 0; a < 2; a++)
#pragma unroll
        for (int b = 0; b < 4; b++)
#pragma unroll
            for (int c = 0; c < 4; c++) acc[a][b][c] = 0.f;

    for (int t = 0; t < NCH; t++) {
        const int p = t & 1;

        // ---- convert & store chunk t (consumes va/vb)
#pragma unroll
        for (int j = 0; j < 4; j++) {        // 4 groups of 8 k's
            uint32_t h[4], l[4];
#pragma unroll
            for (int q = 0; q < 4; q++) {
                float v0 = va[8 * j + 2 * q], v1 = va[8 * j + 2 * q + 1];
                h[q] = pack_bf16(v0, v1);
                float r0 = v0 - __uint_as_float(h[q] << 16);
                float r1 = v1 - __uint_as_float(h[q] & 0xffff0000u);
                l[q] = pack_bf16(r0, r1);
            }
            const uint32_t off = sw64(m, j);
            *(uint4*)(A_HI[p] + off) = make_uint4(h[0], h[1], h[2], h[3]);
            *(uint4*)(A_LO[p] + off) = make_uint4(l[0], l[1], l[2], l[3]);
        }
        {   // B: thread's 8 floats = k group xq of row xb
            float v[8] = {vb[0].x, vb[0].y, vb[0].z, vb[0].w,
                          vb[1].x, vb[1].y, vb[1].z, vb[1].w};
            uint32_t h[4], l[4];
#pragma unroll
            for (int q = 0; q < 4; q++) {
                h[q] = pack_bf16(v[2 * q], v[2 * q + 1]);
                float r0 = v[2 * q]     - __uint_as_float(h[q] << 16);
                float r1 = v[2 * q + 1] - __uint_as_float(h[q] & 0xffff0000u);
                l[q] = pack_bf16(r0, r1);
            }
            const uint32_t off = sw64(xb, xq);
            *(uint4*)(B_HI[p] + off) = make_uint4(h[0], h[1], h[2], h[3]);
            *(uint4*)(B_LO[p] + off) = make_uint4(l[0], l[1], l[2], l[3]);
        }

        __syncthreads();   // buf[p] ready for all warps

        // ---- prefetch chunk t+1 (latency hides under MMA below)
        if (t + 1 < NCH) {
            const float* wp = wbase + (size_t)((t + 1) * 2) * ISTRIDE;
#pragma unroll
            for (int e = 0; e < 32; e++)
                va[e] = wp[(size_t)(e >> 4) * ISTRIDE + (e & 15) * UU];
            const float4* xp = xbase + (t + 1) * (KC / 4);
            vb[0] = xp[0];
            vb[1] = xp[1];
        }

        // ---- MMA: 2 k-tiles of 16
        const uint32_t aHi = smem_u32(A_HI[p]), aLo = smem_u32(A_LO[p]);
        const uint32_t bHi = smem_u32(B_HI[p]), bLo = smem_u32(B_LO[p]);
#pragma unroll
        for (int kt = 0; kt < 2; kt++) {
            uint32_t ahi[2][4], alo[2][4], bhiR[2][4], bloR[2][4];

            const int ar  = (lane & 7) + ((lane >> 3) & 1) * 8;
            const int akg = 2 * kt + (lane >> 4);
#pragma unroll
            for (int m2 = 0; m2 < 2; m2++) {
                const int row = wid * 32 + m2 * 16 + ar;
                const uint32_t off = sw64(row, akg);
                ldsm_x4(ahi[m2], aHi + off);
                ldsm_x4(alo[m2], aLo + off);
            }
            const int bn  = (lane & 7) + ((lane >> 4) & 1) * 8;
            const int bkg = 2 * kt + ((lane >> 3) & 1);
#pragma unroll
            for (int g2 = 0; g2 < 2; g2++) {
                const int n = g2 * 16 + bn;
                const uint32_t off = sw64(n, bkg);
                ldsm_x4(bhiR[g2], bHi + off);
                ldsm_x4(bloR[g2], bLo + off);
            }
#pragma unroll
            for (int m2 = 0; m2 < 2; m2++)
#pragma unroll
                for (int nt = 0; nt < 4; nt++) {
                    const uint32_t bh0 = bhiR[nt >> 1][(nt & 1) * 2];
                    const uint32_t bh1 = bhiR[nt >> 1][(nt & 1) * 2 + 1];
                    const uint32_t bl0 = bloR[nt >> 1][(nt & 1) * 2];
                    const uint32_t bl1 = bloR[nt >> 1][(nt & 1) * 2 + 1];
                    mma_bf16(acc[m2][nt], ahi[m2], bh0, bh1);
                    mma_bf16(acc[m2][nt], alo[m2], bh0, bh1);
                    mma_bf16(acc[m2][nt], ahi[m2], bl0, bl1);
                }
        }
        // no second sync: next iter writes buf[p^1]; buf[p] rewritten only at
        // t+2, by which time every warp has passed sync(t+1) and thus MMA(t).
    }

    // ---- epilogue: D fragments -> g_spart[(mt*KS+ks)][m_local][b]
    float* outp = g_spart + ((size_t)(mt * KS + ks)) * (128 * BB);
#pragma unroll
    for (int m2 = 0; m2 < 2; m2++)
#pragma unroll
        for (int nt = 0; nt < 4; nt++) {
            const int r0 = wid * 32 + m2 * 16 + (lane >> 2);
            const int c  = nt * 8 + 2 * (lane & 3);
            *(float2*)(outp + (size_t)r0 * BB + c) =
                make_float2(acc[m2][nt][0], acc[m2][nt][1]);
            *(float2*)(outp + (size_t)(r0 + 8) * BB + c) =
                make_float2(acc[m2][nt][2], acc[m2][nt][3]);
        }
}

// ---------------------------------------------------------------------------
// Reduce stage 1: grid (OO, NSEG), 1024 threads. Sums KS/NSEG=8 k-splits.
// ---------------------------------------------------------------------------
__global__ void __launch_bounds__(1024) reduce1() {
    const int o = blockIdx.x, seg = blockIdx.y;
    const int t = threadIdx.x;
    const int uu2 = t >> 5, b = t & 31;
    const int mt = o >> 2;
    const int mrow = (o & 3) * 32 + uu2;

    const float* p = g_spart +
        (((size_t)mt * KS + seg * (KS / NSEG)) * 128 + mrow) * BB + b;
    float s = 0.f;
#pragma unroll
    for (int k = 0; k < KS / NSEG; k++)
        s += p[(size_t)k * (128 * BB)];
    g_s1[(((size_t)o * NSEG + seg) * UU + uu2) * BB + b] = s;
}

// ---------------------------------------------------------------------------
// Reduce stage 2 + squash: grid = OO, 1024 threads.
// ---------------------------------------------------------------------------
__global__ void __launch_bounds__(1024) reduce2(float* __restrict__ out) {
    const int o = blockIdx.x;
    const int t = threadIdx.x;
    const int uu2 = t >> 5, b = t & 31;

    __shared__ float sblk[UU * 33];
    __shared__ float scale_s[BB];

    float s = 0.f;
#pragma unroll
    for (int seg = 0; seg < NSEG; seg++)
        s += g_s1[(((size_t)o * NSEG + seg) * UU + uu2) * BB + b];
    sblk[uu2 * 33 + b] = s;
    __syncthreads();

    if (t < BB) {
        float nsq = 0.f;
#pragma unroll
        for (int uv = 0; uv < UU; uv++) {
            float sv = sblk[uv * 33 + t];
            nsq += sv * sv;
        }
        scale_s[t] = sqrtf(nsq) / (1.0f + nsq);
    }
    __syncthreads();

    {   // coalesced output: b2 = t>>5, u2 = t&31
        const int b2 = t >> 5, u2 = t & 31;
        out[(size_t)b2 * (OO * UU) + o * UU + u2] =
            sblk[u2 * 33 + b2] * scale_s[b2];
    }
}

// ---------------------------------------------------------------------------
extern "C" void kernel_launch(void* const* d_in, const int* in_sizes, int n_in,
                              void* d_out, int out_size) {
    const float* x = (const float*)d_in[0];
    const float* w = (const float*)d_in[1];
    if (n_in >= 2 && in_sizes[0] > in_sizes[1]) {   // guard input ordering
        x = (const float*)d_in[1];
        w = (const float*)d_in[0];
    }

    gemm_tc<<<dim3(MT, KS), 128>>>(w, x);
    reduce1<<<dim3(OO, NSEG), 1024>>>();
    reduce2<<<OO, 1024>>>((float*)d_out);
}